// round 15
// baseline (speedup 1.0000x reference)
#include <cuda_runtime.h>
#include <cuda_fp16.h>
#include <math.h>
#include <cstdint>

#define Bsz   64
#define Lseq  512
#define Edim  512
#define Hdim  1024
#define H2    2048

// ---------------------------------------------------------------------------
// Scratch (device globals; no runtime allocation allowed)
// ---------------------------------------------------------------------------
__device__ float g_PRE[4u * 2048u * 2048u]; // split-K partial slabs (small levels only)
__device__ float g_Zb [16384u * 1024u];     // z gate per pair
// fp16 activations / state (the ONLY state representation)
__device__ __half g_Wa [32768u * 512u];
__device__ __half g_H0a[32768u * 1024u];    // state ping
__device__ __half g_H1a[16384u * 1024u];    // state pong
__device__ __half g_Qa [16384u * 2048u];
// Transposed [N,K] weights in fp16 (B operands).
// WzhT: N interleaved as (z_j, h_j). UzrT: N interleaved as (z_j, r_j).
__device__ __half g_WzhT[(size_t)H2 * Edim];
__device__ __half g_UzrT[(size_t)H2 * H2];
__device__ __half g_UhT [(size_t)Hdim * H2];
__device__ float g_bz[Hdim], g_br[Hdim], g_bh[Hdim];

// ---------------------------------------------------------------------------
// Helpers
// ---------------------------------------------------------------------------
__device__ __forceinline__ uint32_t smem_u32(const void* p) {
    uint32_t a;
    asm("{ .reg .u64 t; cvta.to.shared.u64 t, %1; cvt.u32.u64 %0, t; }" : "=r"(a) : "l"(p));
    return a;
}
// SW128 swizzle for 128-byte rows
__device__ __forceinline__ uint32_t swz128(uint32_t byte_off) {
    return byte_off ^ ((byte_off >> 3) & 0x70u);
}
__device__ __forceinline__ void cp16(uint32_t dst, const void* src, uint32_t srcsize) {
    asm volatile("cp.async.cg.shared.global [%0], [%1], 16, %2;"
                 :: "r"(dst), "l"(src), "r"(srcsize));
}
__device__ __forceinline__ void ldsm4(uint32_t* r, uint32_t addr) {
    asm volatile("ldmatrix.sync.aligned.m8n8.x4.shared.b16 {%0,%1,%2,%3}, [%4];"
                 : "=r"(r[0]), "=r"(r[1]), "=r"(r[2]), "=r"(r[3]) : "r"(addr));
}
__device__ __forceinline__ void mma16816(float* d, const uint32_t* a, uint32_t b0, uint32_t b1) {
    asm volatile("mma.sync.aligned.m16n8k16.row.col.f32.f16.f16.f32 "
                 "{%0,%1,%2,%3}, {%4,%5,%6,%7}, {%8,%9}, {%0,%1,%2,%3};"
                 : "+f"(d[0]), "+f"(d[1]), "+f"(d[2]), "+f"(d[3])
                 : "r"(a[0]), "r"(a[1]), "r"(a[2]), "r"(a[3]), "r"(b0), "r"(b1));
}
__device__ __forceinline__ float sigmoidf_(float x) { return 1.f / (1.f + expf(-x)); }

// ---------------------------------------------------------------------------
// Weight packing (interleaved output columns; fp16)
// ---------------------------------------------------------------------------
__global__ void pack_wzhT(const float* __restrict__ Wz, const float* __restrict__ Wh) {
    int idx = blockIdx.x * blockDim.x + threadIdx.x;
    if (idx >= H2 * Edim) return;
    int c = idx / Edim, k = idx - c * Edim;
    int j = c >> 1;
    float v = (c & 1) ? Wh[k * Hdim + j] : Wz[k * Hdim + j];
    g_WzhT[idx] = __float2half_rn(v);
}

__global__ void pack_uzrT(const float* __restrict__ Uzl, const float* __restrict__ Uzr,
                          const float* __restrict__ Url, const float* __restrict__ Urr) {
    int idx = blockIdx.x * blockDim.x + threadIdx.x;
    if (idx >= H2 * H2) return;
    int c = idx >> 11, k = idx & (H2 - 1);
    int j = c >> 1, kk = k & (Hdim - 1);
    float v;
    if ((c & 1) == 0) v = (k < Hdim) ? Uzl[(size_t)k * Hdim + j] : Uzr[(size_t)kk * Hdim + j];
    else              v = (k < Hdim) ? Url[(size_t)k * Hdim + j] : Urr[(size_t)kk * Hdim + j];
    g_UzrT[idx] = __float2half_rn(v);
}

__global__ void pack_uhT(const float* __restrict__ Uhl, const float* __restrict__ Uhr) {
    int idx = blockIdx.x * blockDim.x + threadIdx.x;
    if (idx >= Hdim * H2) return;
    int j = idx >> 11, k = idx & (H2 - 1);
    float v = (k < Hdim) ? Uhl[(size_t)k * Hdim + j] : Uhr[(size_t)(k - Hdim) * Hdim + j];
    g_UhT[idx] = __float2half_rn(v);
}

__global__ void pack_bias(const float* bz, const float* bzl, const float* bzr,
                          const float* br, const float* brl, const float* brr,
                          const float* bh, const float* bhl, const float* bhr) {
    int j = blockIdx.x * blockDim.x + threadIdx.x;
    if (j >= Hdim) return;
    g_bz[j] = bz[j] + bzl[j] + bzr[j];
    g_br[j] = br[j] + brl[j] + brr[j];
    g_bh[j] = bh[j] + bhl[j] + bhr[j];
}

__global__ void gather_fp16(const int* __restrict__ tokens, const float* __restrict__ emb) {
    int t = blockIdx.x * blockDim.x + threadIdx.x;
    if (t >= Bsz * Lseq * (Edim / 2)) return;
    int m = t / (Edim / 2), k2 = (t - m * (Edim / 2)) * 2;
    float2 v = *reinterpret_cast<const float2*>(emb + (size_t)tokens[m] * Edim + k2);
    *reinterpret_cast<__half2*>(&g_Wa[(size_t)m * Edim + k2]) =
        __halves2half2(__float2half_rn(v.x), __float2half_rn(v.y));
}

// ---------------------------------------------------------------------------
// fp16 GEMM (single pass), CTA 128x128, 8 warps (32x64 warp tiles),
// BK=64, 2-stage single-sync cp.async pipeline, split-K via blockIdx.z.
// State is fp16-only (X reads fp16); final fp32 output written when OUT != 0.
// MODE 0: C partial slab. MODE 1: leaf fused. MODE 2: merge1. MODE 3: merge2.
// ---------------------------------------------------------------------------
#define BKE 64
#define STAGE_BYTES 32768
#define OFF_A 0
#define OFF_B 16384
#define GEMM_SMEM (2 * STAGE_BYTES)

template <int MODE>
__global__ __launch_bounds__(256, 2)
void mmagemm(const __half* __restrict__ A,
             const __half* __restrict__ B,
             float* __restrict__ C, int M, int N, int Kfull, int Kp,
             const __half* __restrict__ X,
             float* __restrict__ OUT,
             __half* __restrict__ OUTa) {
    extern __shared__ char smem[];
    const uint32_t sb = smem_u32(smem);
    const int tid = threadIdx.x, wid = tid >> 5, lane = tid & 31;
    const int bm = blockIdx.y * 128, bn = blockIdx.x * 128;
    const int ksl = blockIdx.z;
    const int kbase = ksl * Kp;

    // cp.async mapping: row = tid>>1 (0..127), k-half = (tid&1)*64B, 4x16B each
    const int ld_row = tid >> 1;
    const uint32_t ld_kb = (uint32_t)(tid & 1) * 64u;
    const int a_gr = bm + ld_row;
    const uint32_t a_sz = (a_gr < M) ? 16u : 0u;
    const int a_cl = (a_gr < M) ? a_gr : 0;
    const __half* a_src = A + (size_t)a_cl * Kfull + kbase;
    const __half* b_src = B + (size_t)(bn + ld_row) * Kfull + kbase;
    uint32_t dstj[4];
    #pragma unroll
    for (int j = 0; j < 4; j++)
        dstj[j] = swz128((uint32_t)ld_row * 128u + ld_kb + (uint32_t)j * 16u);
    const int ld_ke = (int)(ld_kb >> 1);

    // ldmatrix base addresses (kb applied per k-step via XOR: the kb bits
    // [6:5] are disjoint from both the base low bits and the swizzle mask
    // source bits [9:7], so swz128(x + kb) == swz128(x) ^ kb).
    const uint32_t a_lr = (uint32_t)(lane & 15);
    const uint32_t a_lb = (uint32_t)(lane >> 4) * 16u;
    const uint32_t b_lr = (uint32_t)((lane & 7) + ((lane >> 4) << 3));
    const uint32_t b_lb = (uint32_t)((lane >> 3) & 1) * 16u;
    const uint32_t wm = (uint32_t)(wid >> 1) * 32u;   // 4 M-groups of 32
    const uint32_t wn = (uint32_t)(wid & 1) * 64u;    // 2 N-groups of 64
    uint32_t bBase[4], aBase[2];
    #pragma unroll
    for (int p = 0; p < 4; p++)
        bBase[p] = OFF_B + swz128((wn + p * 16u + b_lr) * 128u + b_lb);
    #pragma unroll
    for (int mi = 0; mi < 2; mi++)
        aBase[mi] = OFF_A + swz128((wm + mi * 16u + a_lr) * 128u + a_lb);

    float acc[2][8][4];
    #pragma unroll
    for (int i = 0; i < 2; i++)
        #pragma unroll
        for (int j = 0; j < 8; j++)
            #pragma unroll
            for (int q = 0; q < 4; q++) acc[i][j][q] = 0.f;

    const int NC = Kp / BKE;

    auto load_stage = [&](int s, int c) {
        const uint32_t base = sb + (uint32_t)s * STAGE_BYTES;
        const int ke = c * BKE + ld_ke;
        #pragma unroll
        for (int j = 0; j < 4; j++) {
            cp16(base + OFF_A + dstj[j], a_src + ke + j * 8, a_sz);
            cp16(base + OFF_B + dstj[j], b_src + ke + j * 8, 16u);
        }
        asm volatile("cp.async.commit_group;");
    };

    load_stage(0, 0);

    for (int c = 0; c < NC; c++) {
        asm volatile("cp.async.wait_group 0;");
        __syncthreads();
        // Single-sync 2-stage: buffer (c+1)&1 held chunk c-1, whose readers all
        // arrived at this barrier, so the refill needs no second sync.
        if (c + 1 < NC) load_stage((c + 1) & 1, c + 1);

        const uint32_t base = sb + (uint32_t)(c & 1) * STAGE_BYTES;
        #pragma unroll
        for (int ks = 0; ks < 4; ks++) {
            const uint32_t kb = (uint32_t)ks * 32u;
            uint32_t a[8], bh[16];
            #pragma unroll
            for (int p = 0; p < 4; p++)
                ldsm4(&bh[p * 4], base + (bBase[p] ^ kb));
            #pragma unroll
            for (int mi = 0; mi < 2; mi++)
                ldsm4(&a[mi * 4], base + (aBase[mi] ^ kb));
            #pragma unroll
            for (int mi = 0; mi < 2; mi++)
                #pragma unroll
                for (int ni = 0; ni < 8; ni++)
                    mma16816(acc[mi][ni], &a[mi * 4],
                             bh[(ni >> 1) * 4 + (ni & 1) * 2], bh[(ni >> 1) * 4 + (ni & 1) * 2 + 1]);
        }
    }

    // ---------------- Epilogue ----------------
    const int er = lane >> 2, ec = (lane & 3) * 2;
    if (MODE == 0) {
        float* Cs = C + (size_t)ksl * (size_t)M * N;
        #pragma unroll
        for (int mi = 0; mi < 2; mi++) {
            #pragma unroll
            for (int ni = 0; ni < 8; ni++) {
                const int r0 = bm + (int)wm + mi * 16 + er;
                const int col = bn + (int)wn + ni * 8 + ec;
                if (r0 < M)
                    *reinterpret_cast<float2*>(Cs + (size_t)r0 * N + col)
                        = make_float2(acc[mi][ni][0], acc[mi][ni][1]);
                if (r0 + 8 < M)
                    *reinterpret_cast<float2*>(Cs + (size_t)(r0 + 8) * N + col)
                        = make_float2(acc[mi][ni][2], acc[mi][ni][3]);
            }
        }
    } else if (MODE == 1) {
        // leaf: (z,h) pair per thread; h = (1-z)*tanh(h_pre+bh); fp16 state only
        #pragma unroll
        for (int mi = 0; mi < 2; mi++) {
            #pragma unroll
            for (int ni = 0; ni < 8; ni++) {
                const int col = bn + (int)wn + ni * 8 + ec;
                const int j = col >> 1;
                const float bzj = g_bz[j], bhj = g_bh[j];
                #pragma unroll
                for (int rr = 0; rr < 2; rr++) {
                    const int row = bm + (int)wm + mi * 16 + er + rr * 8;
                    float z  = sigmoidf_(acc[mi][ni][rr * 2 + 0] + bzj);
                    float ht = tanhf(acc[mi][ni][rr * 2 + 1] + bhj);
                    OUTa[(size_t)row * Hdim + j] = __float2half_rn((1.f - z) * ht);
                }
            }
        }
    } else if (MODE == 2) {
        // merge1: (z,r) pair; Zb = z, Qa = fp16(r * [hl|hr]), X fp16
        #pragma unroll
        for (int mi = 0; mi < 2; mi++) {
            #pragma unroll
            for (int ni = 0; ni < 8; ni++) {
                const int col = bn + (int)wn + ni * 8 + ec;
                const int j = col >> 1;
                const float bzj = g_bz[j], brj = g_br[j];
                #pragma unroll
                for (int rr = 0; rr < 2; rr++) {
                    const int row = bm + (int)wm + mi * 16 + er + rr * 8;
                    if (row >= M) continue;
                    float z = sigmoidf_(acc[mi][ni][rr * 2 + 0] + bzj);
                    float r = sigmoidf_(acc[mi][ni][rr * 2 + 1] + brj);
                    g_Zb[(size_t)row * Hdim + j] = z;
                    size_t xb = (size_t)row * H2 + j;
                    g_Qa[xb]        = __float2half_rn(r * __half2float(X[xb]));
                    g_Qa[xb + Hdim] = __float2half_rn(r * __half2float(X[xb + Hdim]));
                }
            }
        }
    } else {
        // merge2: h = z*(hl+hr) + (1-z)*tanh(acc+bh); X fp16; OUT fp32 if set
        #pragma unroll
        for (int mi = 0; mi < 2; mi++) {
            #pragma unroll
            for (int ni = 0; ni < 8; ni++) {
                const int col = bn + (int)wn + ni * 8 + ec;
                const float bh0 = g_bh[col], bh1 = g_bh[col + 1];
                #pragma unroll
                for (int rr = 0; rr < 2; rr++) {
                    const int row = bm + (int)wm + mi * 16 + er + rr * 8;
                    if (row >= M) continue;
                    size_t o = (size_t)row * Hdim + col;
                    size_t xb = (size_t)row * H2 + col;
                    float2 z = *reinterpret_cast<const float2*>(&g_Zb[o]);
                    float2 xl = __half22float2(*reinterpret_cast<const __half2*>(&X[xb]));
                    float2 xr = __half22float2(*reinterpret_cast<const __half2*>(&X[xb + Hdim]));
                    float h0 = z.x * (xl.x + xr.x) + (1.f - z.x) * tanhf(acc[mi][ni][rr * 2 + 0] + bh0);
                    float h1 = z.y * (xl.y + xr.y) + (1.f - z.y) * tanhf(acc[mi][ni][rr * 2 + 1] + bh1);
                    *reinterpret_cast<__half2*>(&OUTa[o]) =
                        __halves2half2(__float2half_rn(h0), __float2half_rn(h1));
                    if (OUT)
                        *reinterpret_cast<float2*>(&OUT[o]) = make_float2(h0, h1);
                }
            }
        }
    }
}

// ---------------------------------------------------------------------------
// Elementwise kernels for split-K (small) levels (X is fp16 state)
// ---------------------------------------------------------------------------
__global__ void merge_ew1(const __half* __restrict__ X, int M, int S, int total2) {
    int t = blockIdx.x * blockDim.x + threadIdx.x;
    if (t >= total2) return;
    int m = t >> 9, jj = (t & 511) * 2;
    const size_t slab = (size_t)M * H2;
    size_t pb = (size_t)m * H2 + 2 * jj;  // interleaved (z,r,z,r)
    float4 p = *reinterpret_cast<const float4*>(&g_PRE[pb]);
    for (int s = 1; s < S; s++) {
        float4 q = *reinterpret_cast<const float4*>(&g_PRE[s * slab + pb]);
        p.x += q.x; p.y += q.y; p.z += q.z; p.w += q.w;
    }
    float z0 = sigmoidf_(p.x + g_bz[jj]), r0 = sigmoidf_(p.y + g_br[jj]);
    float z1 = sigmoidf_(p.z + g_bz[jj + 1]), r1 = sigmoidf_(p.w + g_br[jj + 1]);
    *reinterpret_cast<float2*>(&g_Zb[(size_t)m * Hdim + jj]) = make_float2(z0, z1);
    size_t xb = (size_t)m * H2 + jj;
    float2 xl = __half22float2(*reinterpret_cast<const __half2*>(&X[xb]));
    float2 xr = __half22float2(*reinterpret_cast<const __half2*>(&X[xb + Hdim]));
    *reinterpret_cast<__half2*>(&g_Qa[xb]) =
        __halves2half2(__float2half_rn(r0 * xl.x), __float2half_rn(r1 * xl.y));
    *reinterpret_cast<__half2*>(&g_Qa[xb + Hdim]) =
        __halves2half2(__float2half_rn(r0 * xr.x), __float2half_rn(r1 * xr.y));
}

__global__ void merge_ew2(const __half* __restrict__ X, float* __restrict__ OUT,
                          __half* __restrict__ OUTa,
                          int M, int S, int total2) {
    int t = blockIdx.x * blockDim.x + threadIdx.x;
    if (t >= total2) return;
    int m = t >> 9, j = (t & 511) * 2;
    size_t o = (size_t)m * Hdim + j;
    const size_t slab = (size_t)M * Hdim;
    float2 ah = *reinterpret_cast<const float2*>(&g_PRE[o]);
    for (int s = 1; s < S; s++) {
        float2 a = *reinterpret_cast<const float2*>(&g_PRE[s * slab + o]);
        ah.x += a.x; ah.y += a.y;
    }
    size_t xb = (size_t)m * H2 + j;
    float2 z  = *reinterpret_cast<const float2*>(&g_Zb[o]);
    float2 xl = __half22float2(*reinterpret_cast<const __half2*>(&X[xb]));
    float2 xr = __half22float2(*reinterpret_cast<const __half2*>(&X[xb + Hdim]));
    float h0 = z.x * (xl.x + xr.x) + (1.f - z.x) * tanhf(ah.x + g_bh[j]);
    float h1 = z.y * (xl.y + xr.y) + (1.f - z.y) * tanhf(ah.y + g_bh[j + 1]);
    *reinterpret_cast<__half2*>(&OUTa[o]) =
        __halves2half2(__float2half_rn(h0), __float2half_rn(h1));
    if (OUT)
        *reinterpret_cast<float2*>(&OUT[o]) = make_float2(h0, h1);
}

// ---------------------------------------------------------------------------
// Launch
// ---------------------------------------------------------------------------
extern "C" void kernel_launch(void* const* d_in, const int* in_sizes, int n_in,
                              void* d_out, int out_size) {
    const int*   tokens = (const int*)  d_in[0];
    const float* emb    = (const float*)d_in[1];
    const float* W_z  = (const float*)d_in[2];
    const float* b_z  = (const float*)d_in[3];
    const float* U_zl = (const float*)d_in[4];
    const float* b_zl = (const float*)d_in[5];
    const float* U_zr = (const float*)d_in[6];
    const float* b_zr = (const float*)d_in[7];
    const float* b_r  = (const float*)d_in[9];
    const float* U_rl = (const float*)d_in[10];
    const float* b_rl = (const float*)d_in[11];
    const float* U_rr = (const float*)d_in[12];
    const float* b_rr = (const float*)d_in[13];
    const float* W_h  = (const float*)d_in[14];
    const float* b_h  = (const float*)d_in[15];
    const float* U_hl = (const float*)d_in[16];
    const float* b_hl = (const float*)d_in[17];
    const float* U_hr = (const float*)d_in[18];
    const float* b_hr = (const float*)d_in[19];

    float* PRE;
    __half *Wa, *H0a, *H1a, *Qa, *WzhT, *UzrT, *UhT;
    cudaGetSymbolAddress((void**)&PRE, g_PRE);
    cudaGetSymbolAddress((void**)&Wa,  g_Wa);
    cudaGetSymbolAddress((void**)&H0a, g_H0a);
    cudaGetSymbolAddress((void**)&H1a, g_H1a);
    cudaGetSymbolAddress((void**)&Qa,  g_Qa);
    cudaGetSymbolAddress((void**)&WzhT, g_WzhT);
    cudaGetSymbolAddress((void**)&UzrT, g_UzrT);
    cudaGetSymbolAddress((void**)&UhT,  g_UhT);

    cudaFuncSetAttribute(mmagemm<0>, cudaFuncAttributeMaxDynamicSharedMemorySize, GEMM_SMEM);
    cudaFuncSetAttribute(mmagemm<1>, cudaFuncAttributeMaxDynamicSharedMemorySize, GEMM_SMEM);
    cudaFuncSetAttribute(mmagemm<2>, cudaFuncAttributeMaxDynamicSharedMemorySize, GEMM_SMEM);
    cudaFuncSetAttribute(mmagemm<3>, cudaFuncAttributeMaxDynamicSharedMemorySize, GEMM_SMEM);

    const int Mleaf = Bsz * Lseq;  // 32768

    // Order chosen so the leaf GEMM is launch index 3 (the one ncu captures).
    pack_bias<<<(Hdim + 255) / 256, 256>>>(b_z, b_zl, b_zr, b_r, b_rl, b_rr, b_h, b_hl, b_hr);
    pack_wzhT<<<(H2 * Edim + 255) / 256, 256>>>(W_z, W_h);
    gather_fp16<<<(Mleaf * (Edim / 2) + 255) / 256, 256>>>(tokens, emb);

    {   // leaf fused: H0a = fp16((1-z)*tanh(.))
        dim3 grid(H2 / 128, Mleaf / 128, 1);
        mmagemm<1><<<grid, 256, GEMM_SMEM>>>(Wa, WzhT, nullptr,
                                             Mleaf, H2, Edim, Edim,
                                             nullptr, nullptr, H0a);
    }

    pack_uzrT<<<(H2 * H2 + 255) / 256, 256>>>(U_zl, U_zr, U_rl, U_rr);
    pack_uhT <<<(Hdim * H2 + 255) / 256, 256>>>(U_hl, U_hr);

    // --- merge levels ---
    __half* cura = H0a;
    for (int n = Lseq; n > 1; n >>= 1) {
        const int M = Bsz * (n / 2);
        const bool last = (n == 2);
        __half* outa = (cura == H0a) ? H1a : H0a;
        float* outf = last ? (float*)d_out : nullptr;
        const int total2 = M * (Hdim / 2);
        const int gy = (M + 127) / 128;

        if (M >= 2048) {
            dim3 g1(H2 / 128, gy, 1);
            mmagemm<2><<<g1, 256, GEMM_SMEM>>>(cura, UzrT, nullptr,
                                               M, H2, H2, H2, cura, nullptr, nullptr);
            dim3 g2(Hdim / 128, gy, 1);
            mmagemm<3><<<g2, 256, GEMM_SMEM>>>(Qa, UhT, nullptr,
                                               M, Hdim, H2, H2, cura, outf, outa);
        } else {
            int S = 2048 / M; if (S > 16) S = 16;
            const int Kp = H2 / S;
            dim3 g1(H2 / 128, gy, S);
            mmagemm<0><<<g1, 256, GEMM_SMEM>>>(cura, UzrT, PRE,
                                               M, H2, H2, Kp, nullptr, nullptr, nullptr);
            merge_ew1<<<(total2 + 255) / 256, 256>>>(cura, M, S, total2);
            dim3 g2(Hdim / 128, gy, S);
            mmagemm<0><<<g2, 256, GEMM_SMEM>>>(Qa, UhT, PRE,
                                               M, Hdim, H2, Kp, nullptr, nullptr, nullptr);
            merge_ew2<<<(total2 + 255) / 256, 256>>>(cura, outf, outa, M, S, total2);
        }
        cura = outa;
    }
}

// round 16
// speedup vs baseline: 1.5428x; 1.5428x over previous
#include <cuda_runtime.h>
#include <cuda_fp16.h>
#include <math.h>
#include <cstdint>

#define Bsz   64
#define Lseq  512
#define Edim  512
#define Hdim  1024
#define H2    2048

// ---------------------------------------------------------------------------
// Scratch (device globals; no runtime allocation allowed)
// ---------------------------------------------------------------------------
__device__ float g_PRE[4u * 2048u * 2048u]; // split-K partial slabs (small levels only)
__device__ float g_Zb [16384u * 1024u];     // z gate per pair
// fp16 activations / state (the ONLY state representation)
__device__ __half g_Wa [32768u * 512u];
__device__ __half g_H0a[32768u * 1024u];    // state ping
__device__ __half g_H1a[16384u * 1024u];    // state pong
__device__ __half g_Qa [16384u * 2048u];
// Transposed [N,K] weights in fp16 (B operands).
// WzhT: N interleaved as (z_j, h_j). UzrT: N interleaved as (z_j, r_j).
__device__ __half g_WzhT[(size_t)H2 * Edim];
__device__ __half g_UzrT[(size_t)H2 * H2];
__device__ __half g_UhT [(size_t)Hdim * H2];
__device__ float g_bz[Hdim], g_br[Hdim], g_bh[Hdim];

// ---------------------------------------------------------------------------
// Helpers
// ---------------------------------------------------------------------------
__device__ __forceinline__ uint32_t smem_u32(const void* p) {
    uint32_t a;
    asm("{ .reg .u64 t; cvta.to.shared.u64 t, %1; cvt.u32.u64 %0, t; }" : "=r"(a) : "l"(p));
    return a;
}
// SW128 swizzle for 128-byte rows
__device__ __forceinline__ uint32_t swz128(uint32_t byte_off) {
    return byte_off ^ ((byte_off >> 3) & 0x70u);
}
__device__ __forceinline__ void cp16(uint32_t dst, const void* src, uint32_t srcsize) {
    asm volatile("cp.async.cg.shared.global [%0], [%1], 16, %2;"
                 :: "r"(dst), "l"(src), "r"(srcsize));
}
__device__ __forceinline__ void ldsm4(uint32_t* r, uint32_t addr) {
    asm volatile("ldmatrix.sync.aligned.m8n8.x4.shared.b16 {%0,%1,%2,%3}, [%4];"
                 : "=r"(r[0]), "=r"(r[1]), "=r"(r[2]), "=r"(r[3]) : "r"(addr));
}
__device__ __forceinline__ void mma16816(float* d, const uint32_t* a, uint32_t b0, uint32_t b1) {
    asm volatile("mma.sync.aligned.m16n8k16.row.col.f32.f16.f16.f32 "
                 "{%0,%1,%2,%3}, {%4,%5,%6,%7}, {%8,%9}, {%0,%1,%2,%3};"
                 : "+f"(d[0]), "+f"(d[1]), "+f"(d[2]), "+f"(d[3])
                 : "r"(a[0]), "r"(a[1]), "r"(a[2]), "r"(a[3]), "r"(b0), "r"(b1));
}
__device__ __forceinline__ float sigmoidf_(float x) { return 1.f / (1.f + expf(-x)); }

// ---------------------------------------------------------------------------
// Weight packing (interleaved output columns; fp16)
// ---------------------------------------------------------------------------
__global__ void pack_wzhT(const float* __restrict__ Wz, const float* __restrict__ Wh) {
    int idx = blockIdx.x * blockDim.x + threadIdx.x;
    if (idx >= H2 * Edim) return;
    int c = idx / Edim, k = idx - c * Edim;
    int j = c >> 1;
    float v = (c & 1) ? Wh[k * Hdim + j] : Wz[k * Hdim + j];
    g_WzhT[idx] = __float2half_rn(v);
}

__global__ void pack_uzrT(const float* __restrict__ Uzl, const float* __restrict__ Uzr,
                          const float* __restrict__ Url, const float* __restrict__ Urr) {
    int idx = blockIdx.x * blockDim.x + threadIdx.x;
    if (idx >= H2 * H2) return;
    int c = idx >> 11, k = idx & (H2 - 1);
    int j = c >> 1, kk = k & (Hdim - 1);
    float v;
    if ((c & 1) == 0) v = (k < Hdim) ? Uzl[(size_t)k * Hdim + j] : Uzr[(size_t)kk * Hdim + j];
    else              v = (k < Hdim) ? Url[(size_t)k * Hdim + j] : Urr[(size_t)kk * Hdim + j];
    g_UzrT[idx] = __float2half_rn(v);
}

__global__ void pack_uhT(const float* __restrict__ Uhl, const float* __restrict__ Uhr) {
    int idx = blockIdx.x * blockDim.x + threadIdx.x;
    if (idx >= Hdim * H2) return;
    int j = idx >> 11, k = idx & (H2 - 1);
    float v = (k < Hdim) ? Uhl[(size_t)k * Hdim + j] : Uhr[(size_t)(k - Hdim) * Hdim + j];
    g_UhT[idx] = __float2half_rn(v);
}

__global__ void pack_bias(const float* bz, const float* bzl, const float* bzr,
                          const float* br, const float* brl, const float* brr,
                          const float* bh, const float* bhl, const float* bhr) {
    int j = blockIdx.x * blockDim.x + threadIdx.x;
    if (j >= Hdim) return;
    g_bz[j] = bz[j] + bzl[j] + bzr[j];
    g_br[j] = br[j] + brl[j] + brr[j];
    g_bh[j] = bh[j] + bhl[j] + bhr[j];
}

__global__ void gather_fp16(const int* __restrict__ tokens, const float* __restrict__ emb) {
    int t = blockIdx.x * blockDim.x + threadIdx.x;
    if (t >= Bsz * Lseq * (Edim / 2)) return;
    int m = t / (Edim / 2), k2 = (t - m * (Edim / 2)) * 2;
    float2 v = *reinterpret_cast<const float2*>(emb + (size_t)tokens[m] * Edim + k2);
    *reinterpret_cast<__half2*>(&g_Wa[(size_t)m * Edim + k2]) =
        __halves2half2(__float2half_rn(v.x), __float2half_rn(v.y));
}

// ---------------------------------------------------------------------------
// fp16 GEMM (single pass), CTA 128x128, 8 warps (32x64 warp tiles),
// BK=64, 2-stage single-sync cp.async pipeline, split-K via blockIdx.z.
// State is fp16-only (X reads fp16); final fp32 output written when OUT != 0.
// MODE 0: C partial slab. MODE 1: leaf fused. MODE 2: merge1. MODE 3: merge2.
// ---------------------------------------------------------------------------
#define BKE 64
#define STAGE_BYTES 32768
#define OFF_A 0
#define OFF_B 16384
#define GEMM_SMEM (2 * STAGE_BYTES)

template <int MODE>
__global__ __launch_bounds__(256, 2)
void mmagemm(const __half* __restrict__ A,
             const __half* __restrict__ B,
             float* __restrict__ C, int M, int N, int Kfull, int Kp,
             const __half* __restrict__ X,
             float* __restrict__ OUT,
             __half* __restrict__ OUTa) {
    extern __shared__ char smem[];
    const uint32_t sb = smem_u32(smem);
    const int tid = threadIdx.x, wid = tid >> 5, lane = tid & 31;
    const int bm = blockIdx.y * 128, bn = blockIdx.x * 128;
    const int ksl = blockIdx.z;
    const int kbase = ksl * Kp;

    // cp.async mapping: row = tid>>1 (0..127), k-half = (tid&1)*64B, 4x16B each
    const int ld_row = tid >> 1;
    const uint32_t ld_kb = (uint32_t)(tid & 1) * 64u;
    const int a_gr = bm + ld_row;
    const uint32_t a_sz = (a_gr < M) ? 16u : 0u;
    const int a_cl = (a_gr < M) ? a_gr : 0;
    const __half* a_src = A + (size_t)a_cl * Kfull + kbase;
    const __half* b_src = B + (size_t)(bn + ld_row) * Kfull + kbase;
    uint32_t dstj[4];
    #pragma unroll
    for (int j = 0; j < 4; j++)
        dstj[j] = swz128((uint32_t)ld_row * 128u + ld_kb + (uint32_t)j * 16u);
    const int ld_ke = (int)(ld_kb >> 1);

    // ldmatrix base addresses (kb applied per k-step via XOR: kb bits [5:6]
    // are zero in the base and outside the swizzle-source bits [7:9], so
    // swz128(x + kb) == swz128(x) ^ kb).
    const uint32_t a_lr = (uint32_t)(lane & 15);
    const uint32_t a_lb = (uint32_t)(lane >> 4) * 16u;
    const uint32_t b_lr = (uint32_t)((lane & 7) + ((lane >> 4) << 3));
    const uint32_t b_lb = (uint32_t)((lane >> 3) & 1) * 16u;
    const uint32_t wm = (uint32_t)(wid >> 1) * 32u;   // 4 M-groups of 32
    const uint32_t wn = (uint32_t)(wid & 1) * 64u;    // 2 N-groups of 64
    uint32_t bBase[4], aBase[2];
    #pragma unroll
    for (int p = 0; p < 4; p++)
        bBase[p] = OFF_B + swz128((wn + p * 16u + b_lr) * 128u + b_lb);
    #pragma unroll
    for (int mi = 0; mi < 2; mi++)
        aBase[mi] = OFF_A + swz128((wm + mi * 16u + a_lr) * 128u + a_lb);

    float acc[2][8][4];
    #pragma unroll
    for (int i = 0; i < 2; i++)
        #pragma unroll
        for (int j = 0; j < 8; j++)
            #pragma unroll
            for (int q = 0; q < 4; q++) acc[i][j][q] = 0.f;

    const int NC = Kp / BKE;

    auto load_stage = [&](int s, int c) {
        const uint32_t base = sb + (uint32_t)s * STAGE_BYTES;
        const int ke = c * BKE + ld_ke;
        #pragma unroll
        for (int j = 0; j < 4; j++) {
            cp16(base + OFF_A + dstj[j], a_src + ke + j * 8, a_sz);
            cp16(base + OFF_B + dstj[j], b_src + ke + j * 8, 16u);
        }
        asm volatile("cp.async.commit_group;");
    };

    load_stage(0, 0);

    for (int c = 0; c < NC; c++) {
        asm volatile("cp.async.wait_group 0;");
        __syncthreads();
        // Single-sync 2-stage: buffer (c+1)&1 held chunk c-1, whose readers all
        // arrived at this barrier, so the refill needs no second sync.
        if (c + 1 < NC) load_stage((c + 1) & 1, c + 1);

        const uint32_t base = sb + (uint32_t)(c & 1) * STAGE_BYTES;
        #pragma unroll
        for (int ks = 0; ks < 4; ks++) {
            const uint32_t kb = (uint32_t)ks * 32u;
            uint32_t a[8], bh[16];
            #pragma unroll
            for (int p = 0; p < 4; p++)
                ldsm4(&bh[p * 4], base + (bBase[p] ^ kb));
            #pragma unroll
            for (int mi = 0; mi < 2; mi++)
                ldsm4(&a[mi * 4], base + (aBase[mi] ^ kb));
            #pragma unroll
            for (int mi = 0; mi < 2; mi++)
                #pragma unroll
                for (int ni = 0; ni < 8; ni++)
                    mma16816(acc[mi][ni], &a[mi * 4],
                             bh[(ni >> 1) * 4 + (ni & 1) * 2], bh[(ni >> 1) * 4 + (ni & 1) * 2 + 1]);
        }
    }

    // ---------------- Epilogue ----------------
    const int er = lane >> 2, ec = (lane & 3) * 2;
    if (MODE == 0) {
        float* Cs = C + (size_t)ksl * (size_t)M * N;
        #pragma unroll
        for (int mi = 0; mi < 2; mi++) {
            #pragma unroll
            for (int ni = 0; ni < 8; ni++) {
                const int r0 = bm + (int)wm + mi * 16 + er;
                const int col = bn + (int)wn + ni * 8 + ec;
                if (r0 < M)
                    *reinterpret_cast<float2*>(Cs + (size_t)r0 * N + col)
                        = make_float2(acc[mi][ni][0], acc[mi][ni][1]);
                if (r0 + 8 < M)
                    *reinterpret_cast<float2*>(Cs + (size_t)(r0 + 8) * N + col)
                        = make_float2(acc[mi][ni][2], acc[mi][ni][3]);
            }
        }
    } else if (MODE == 1) {
        // leaf: (z,h) pair per thread; h = (1-z)*tanh(h_pre+bh); fp16 state only
        #pragma unroll
        for (int mi = 0; mi < 2; mi++) {
            #pragma unroll
            for (int ni = 0; ni < 8; ni++) {
                const int col = bn + (int)wn + ni * 8 + ec;
                const int j = col >> 1;
                const float bzj = g_bz[j], bhj = g_bh[j];
                #pragma unroll
                for (int rr = 0; rr < 2; rr++) {
                    const int row = bm + (int)wm + mi * 16 + er + rr * 8;
                    float z  = sigmoidf_(acc[mi][ni][rr * 2 + 0] + bzj);
                    float ht = tanhf(acc[mi][ni][rr * 2 + 1] + bhj);
                    OUTa[(size_t)row * Hdim + j] = __float2half_rn((1.f - z) * ht);
                }
            }
        }
    } else if (MODE == 2) {
        // merge1: (z,r) pair; Zb = z, Qa = fp16(r * [hl|hr]), X fp16
        #pragma unroll
        for (int mi = 0; mi < 2; mi++) {
            #pragma unroll
            for (int ni = 0; ni < 8; ni++) {
                const int col = bn + (int)wn + ni * 8 + ec;
                const int j = col >> 1;
                const float bzj = g_bz[j], brj = g_br[j];
                #pragma unroll
                for (int rr = 0; rr < 2; rr++) {
                    const int row = bm + (int)wm + mi * 16 + er + rr * 8;
                    if (row >= M) continue;
                    float z = sigmoidf_(acc[mi][ni][rr * 2 + 0] + bzj);
                    float r = sigmoidf_(acc[mi][ni][rr * 2 + 1] + brj);
                    g_Zb[(size_t)row * Hdim + j] = z;
                    size_t xb = (size_t)row * H2 + j;
                    g_Qa[xb]        = __float2half_rn(r * __half2float(X[xb]));
                    g_Qa[xb + Hdim] = __float2half_rn(r * __half2float(X[xb + Hdim]));
                }
            }
        }
    } else {
        // merge2: h = z*(hl+hr) + (1-z)*tanh(acc+bh); X fp16; OUT fp32 if set
        #pragma unroll
        for (int mi = 0; mi < 2; mi++) {
            #pragma unroll
            for (int ni = 0; ni < 8; ni++) {
                const int col = bn + (int)wn + ni * 8 + ec;
                const float bh0 = g_bh[col], bh1 = g_bh[col + 1];
                #pragma unroll
                for (int rr = 0; rr < 2; rr++) {
                    const int row = bm + (int)wm + mi * 16 + er + rr * 8;
                    if (row >= M) continue;
                    size_t o = (size_t)row * Hdim + col;
                    size_t xb = (size_t)row * H2 + col;
                    float2 z = *reinterpret_cast<const float2*>(&g_Zb[o]);
                    float2 xl = __half22float2(*reinterpret_cast<const __half2*>(&X[xb]));
                    float2 xr = __half22float2(*reinterpret_cast<const __half2*>(&X[xb + Hdim]));
                    float h0 = z.x * (xl.x + xr.x) + (1.f - z.x) * tanhf(acc[mi][ni][rr * 2 + 0] + bh0);
                    float h1 = z.y * (xl.y + xr.y) + (1.f - z.y) * tanhf(acc[mi][ni][rr * 2 + 1] + bh1);
                    *reinterpret_cast<__half2*>(&OUTa[o]) =
                        __halves2half2(__float2half_rn(h0), __float2half_rn(h1));
                    if (OUT)
                        *reinterpret_cast<float2*>(&OUT[o]) = make_float2(h0, h1);
                }
            }
        }
    }
}

// ---------------------------------------------------------------------------
// Elementwise kernels for split-K (small) levels (X is fp16 state)
// ---------------------------------------------------------------------------
__global__ void merge_ew1(const __half* __restrict__ X, int M, int S, int total2) {
    int t = blockIdx.x * blockDim.x + threadIdx.x;
    if (t >= total2) return;
    int m = t >> 9, jj = (t & 511) * 2;
    const size_t slab = (size_t)M * H2;
    size_t pb = (size_t)m * H2 + 2 * jj;  // interleaved (z,r,z,r)
    float4 p = *reinterpret_cast<const float4*>(&g_PRE[pb]);
    for (int s = 1; s < S; s++) {
        float4 q = *reinterpret_cast<const float4*>(&g_PRE[s * slab + pb]);
        p.x += q.x; p.y += q.y; p.z += q.z; p.w += q.w;
    }
    float z0 = sigmoidf_(p.x + g_bz[jj]), r0 = sigmoidf_(p.y + g_br[jj]);
    float z1 = sigmoidf_(p.z + g_bz[jj + 1]), r1 = sigmoidf_(p.w + g_br[jj + 1]);
    *reinterpret_cast<float2*>(&g_Zb[(size_t)m * Hdim + jj]) = make_float2(z0, z1);
    size_t xb = (size_t)m * H2 + jj;
    float2 xl = __half22float2(*reinterpret_cast<const __half2*>(&X[xb]));
    float2 xr = __half22float2(*reinterpret_cast<const __half2*>(&X[xb + Hdim]));
    *reinterpret_cast<__half2*>(&g_Qa[xb]) =
        __halves2half2(__float2half_rn(r0 * xl.x), __float2half_rn(r1 * xl.y));
    *reinterpret_cast<__half2*>(&g_Qa[xb + Hdim]) =
        __halves2half2(__float2half_rn(r0 * xr.x), __float2half_rn(r1 * xr.y));
}

__global__ void merge_ew2(const __half* __restrict__ X, float* __restrict__ OUT,
                          __half* __restrict__ OUTa,
                          int M, int S, int total2) {
    int t = blockIdx.x * blockDim.x + threadIdx.x;
    if (t >= total2) return;
    int m = t >> 9, j = (t & 511) * 2;
    size_t o = (size_t)m * Hdim + j;
    const size_t slab = (size_t)M * Hdim;
    float2 ah = *reinterpret_cast<const float2*>(&g_PRE[o]);
    for (int s = 1; s < S; s++) {
        float2 a = *reinterpret_cast<const float2*>(&g_PRE[s * slab + o]);
        ah.x += a.x; ah.y += a.y;
    }
    size_t xb = (size_t)m * H2 + j;
    float2 z  = *reinterpret_cast<const float2*>(&g_Zb[o]);
    float2 xl = __half22float2(*reinterpret_cast<const __half2*>(&X[xb]));
    float2 xr = __half22float2(*reinterpret_cast<const __half2*>(&X[xb + Hdim]));
    float h0 = z.x * (xl.x + xr.x) + (1.f - z.x) * tanhf(ah.x + g_bh[j]);
    float h1 = z.y * (xl.y + xr.y) + (1.f - z.y) * tanhf(ah.y + g_bh[j + 1]);
    *reinterpret_cast<__half2*>(&OUTa[o]) =
        __halves2half2(__float2half_rn(h0), __float2half_rn(h1));
    if (OUT)
        *reinterpret_cast<float2*>(&OUT[o]) = make_float2(h0, h1);
}

// ---------------------------------------------------------------------------
// Launch
// ---------------------------------------------------------------------------
extern "C" void kernel_launch(void* const* d_in, const int* in_sizes, int n_in,
                              void* d_out, int out_size) {
    const int*   tokens = (const int*)  d_in[0];
    const float* emb    = (const float*)d_in[1];
    const float* W_z  = (const float*)d_in[2];
    const float* b_z  = (const float*)d_in[3];
    const float* U_zl = (const float*)d_in[4];
    const float* b_zl = (const float*)d_in[5];
    const float* U_zr = (const float*)d_in[6];
    const float* b_zr = (const float*)d_in[7];
    const float* b_r  = (const float*)d_in[9];
    const float* U_rl = (const float*)d_in[10];
    const float* b_rl = (const float*)d_in[11];
    const float* U_rr = (const float*)d_in[12];
    const float* b_rr = (const float*)d_in[13];
    const float* W_h  = (const float*)d_in[14];
    const float* b_h  = (const float*)d_in[15];
    const float* U_hl = (const float*)d_in[16];
    const float* b_hl = (const float*)d_in[17];
    const float* U_hr = (const float*)d_in[18];
    const float* b_hr = (const float*)d_in[19];

    float* PRE;
    __half *Wa, *H0a, *H1a, *Qa, *WzhT, *UzrT, *UhT;
    cudaGetSymbolAddress((void**)&PRE, g_PRE);
    cudaGetSymbolAddress((void**)&Wa,  g_Wa);
    cudaGetSymbolAddress((void**)&H0a, g_H0a);
    cudaGetSymbolAddress((void**)&H1a, g_H1a);
    cudaGetSymbolAddress((void**)&Qa,  g_Qa);
    cudaGetSymbolAddress((void**)&WzhT, g_WzhT);
    cudaGetSymbolAddress((void**)&UzrT, g_UzrT);
    cudaGetSymbolAddress((void**)&UhT,  g_UhT);

    cudaFuncSetAttribute(mmagemm<0>, cudaFuncAttributeMaxDynamicSharedMemorySize, GEMM_SMEM);
    cudaFuncSetAttribute(mmagemm<1>, cudaFuncAttributeMaxDynamicSharedMemorySize, GEMM_SMEM);
    cudaFuncSetAttribute(mmagemm<2>, cudaFuncAttributeMaxDynamicSharedMemorySize, GEMM_SMEM);
    cudaFuncSetAttribute(mmagemm<3>, cudaFuncAttributeMaxDynamicSharedMemorySize, GEMM_SMEM);

    const int Mleaf = Bsz * Lseq;  // 32768

    // Order chosen so the leaf GEMM is launch index 3 (the one ncu captures).
    pack_bias<<<(Hdim + 255) / 256, 256>>>(b_z, b_zl, b_zr, b_r, b_rl, b_rr, b_h, b_hl, b_hr);
    pack_wzhT<<<(H2 * Edim + 255) / 256, 256>>>(W_z, W_h);
    gather_fp16<<<(Mleaf * (Edim / 2) + 255) / 256, 256>>>(tokens, emb);

    {   // leaf fused: H0a = fp16((1-z)*tanh(.))
        dim3 grid(H2 / 128, Mleaf / 128, 1);
        mmagemm<1><<<grid, 256, GEMM_SMEM>>>(Wa, WzhT, nullptr,
                                             Mleaf, H2, Edim, Edim,
                                             nullptr, nullptr, H0a);
    }

    pack_uzrT<<<(H2 * H2 + 255) / 256, 256>>>(U_zl, U_zr, U_rl, U_rr);
    pack_uhT <<<(Hdim * H2 + 255) / 256, 256>>>(U_hl, U_hr);

    // --- merge levels ---
    __half* cura = H0a;
    for (int n = Lseq; n > 1; n >>= 1) {
        const int M = Bsz * (n / 2);
        const bool last = (n == 2);
        __half* outa = (cura == H0a) ? H1a : H0a;
        float* outf = last ? (float*)d_out : nullptr;
        const int total2 = M * (Hdim / 2);
        const int gy = (M + 127) / 128;

        if (M >= 2048) {
            dim3 g1(H2 / 128, gy, 1);
            mmagemm<2><<<g1, 256, GEMM_SMEM>>>(cura, UzrT, nullptr,
                                               M, H2, H2, H2, cura, nullptr, nullptr);
            dim3 g2(Hdim / 128, gy, 1);
            mmagemm<3><<<g2, 256, GEMM_SMEM>>>(Qa, UhT, nullptr,
                                               M, Hdim, H2, H2, cura, outf, outa);
        } else {
            int S = 2048 / M; if (S > 16) S = 16;
            const int Kp = H2 / S;
            dim3 g1(H2 / 128, gy, S);
            mmagemm<0><<<g1, 256, GEMM_SMEM>>>(cura, UzrT, PRE,
                                               M, H2, H2, Kp, nullptr, nullptr, nullptr);
            merge_ew1<<<(total2 + 255) / 256, 256>>>(cura, M, S, total2);
            dim3 g2(Hdim / 128, gy, S);
            mmagemm<0><<<g2, 256, GEMM_SMEM>>>(Qa, UhT, PRE,
                                               M, Hdim, H2, Kp, nullptr, nullptr, nullptr);
            merge_ew2<<<(total2 + 255) / 256, 256>>>(cura, outf, outa, M, S, total2);
        }
        cura = outa;
    }
}